// round 5
// baseline (speedup 1.0000x reference)
#include <cuda_runtime.h>
typedef unsigned long long u64t;

#define NT 2
#define NPER 256
#define FIT_IN 1600
#define FH 240
#define BB 4
#define NROWS 2048

__device__ __align__(16) float g_DR[(size_t)NROWS * FIT_IN];

__device__ __forceinline__ float tanhe(float x) {
    float xa = fminf(fmaxf(x, -15.f), 15.f);
    float t = __expf(2.f * xa);
    return __fdividef(t - 1.f, t + 1.f);
}
__device__ __forceinline__ u64t pack2(float lo, float hi) {
    u64t r; asm("mov.b64 %0, {%1,%2};" : "=l"(r) : "f"(lo), "f"(hi)); return r;
}
__device__ __forceinline__ void unpack2(u64t v, float& lo, float& hi) {
    asm("mov.b64 {%0,%1}, %2;" : "=f"(lo), "=f"(hi) : "l"(v));
}
__device__ __forceinline__ u64t ffma2(u64t a, u64t b, u64t c) {
    u64t d; asm("fma.rn.f32x2 %0, %1, %2, %3;" : "=l"(d) : "l"(a), "l"(b), "l"(c)); return d;
}
__device__ __forceinline__ float pget(const u64t* p, int k) {
    float l, h; unpack2(p[k >> 1], l, h); return (k & 1) ? h : l;
}
__device__ __forceinline__ unsigned smaddr(const void* p) {
    unsigned a;
    asm("{.reg .u64 t; cvta.to.shared.u64 t, %1; cvt.u32.u64 %0, t;}" : "=r"(a) : "l"(p));
    return a;
}
__device__ __forceinline__ void cp16(unsigned dst, const void* src) {
    asm volatile("cp.async.ca.shared.global [%0], [%1], 16;" :: "r"(dst), "l"(src));
}
__device__ __forceinline__ void cp_commit() {
    asm volatile("cp.async.commit_group;" ::: "memory");
}

// ================= Kernel A: embedding + einsum + DR (f32x2) =================
// smem float offsets
#define AW0   0       // 28 (25 + zero pad)
#define AB0   28      // 28
#define AW1T  56      // [50][28]  W1^T, k-pad zero  (rows 112B, 16B aligned)
#define AB1   1456    // 52
#define AW2T  1508    // [100][52] W2^T, k-pad zero  (rows 208B, 16B aligned)
#define AB2   6708    // 100
#define AGT   6808    // [100][132] G transposed (row = g, cols = m)
#define ABLKT 20008   // [4][128]   blk transposed (row = c, cols = m)
#define AXYZ  20520   // [4][100]
#define AH1   20920   // [128][50]  h1 values for residual reads
#define A_SMEM 27320  // floats = 109280 B -> 2 blocks/SM

__global__ void __launch_bounds__(128, 2) emb_dr_kernel(
    const float* __restrict__ Ri,
    const float* __restrict__ eW0, const float* __restrict__ eB0,
    const float* __restrict__ eW1, const float* __restrict__ eB1,
    const float* __restrict__ eW2, const float* __restrict__ eB2)
{
    extern __shared__ float sm[];
    const int t = threadIdx.x;
    const int blk = blockIdx.x;
    const int n = blk & 255;
    const int b = (blk >> 8) & 3;
    const int i = blk >> 10;

    const float* ri_base = Ri + ((size_t)((b * NT + i) * NPER + n)) * (NT * 128) * 4;

    u64t axyz[4] = {0ull, 0ull, 0ull, 0ull};

#pragma unroll 1
    for (int j = 0; j < NT; ++j) {
        __syncthreads();   // prior einsum reads complete before restage
        const int e = i * NT + j;
        if (t < 28) {
            sm[AW0 + t] = (t < 25) ? eW0[e * 25 + t] : 0.f;
            sm[AB0 + t] = (t < 25) ? eB0[e * 25 + t] : 0.f;
        }
        for (int x = t; x < 1250; x += 128) { int k = x / 50, g = x - 50 * k; sm[AW1T + g * 28 + k] = eW1[e * 1250 + x]; }
        for (int x = t; x < 150;  x += 128) { int g = x / 3,  p = x - 3 * g;  sm[AW1T + g * 28 + 25 + p] = 0.f; }
        if (t < 50) sm[AB1 + t] = eB1[e * 50 + t];
        for (int x = t; x < 5000; x += 128) { int k = x / 100, g = x - 100 * k; sm[AW2T + g * 52 + k] = eW2[e * 5000 + x]; }
        for (int x = t; x < 200;  x += 128) { int g = x >> 1, p = x & 1; sm[AW2T + g * 52 + 50 + p] = 0.f; }
        if (t < 100) sm[AB2 + t] = eB2[e * 100 + t];
        float4 rv = *(const float4*)(ri_base + (size_t)(j * 128 + t) * 4);
        sm[ABLKT + 0 * 128 + t] = rv.x;
        sm[ABLKT + 1 * 128 + t] = rv.y;
        sm[ABLKT + 2 * 128 + t] = rv.z;
        sm[ABLKT + 3 * 128 + t] = rv.w;
        __syncthreads();

        // ---- h0 (25) packed; pad entries give tanh(0)=0 ----
        const float s = rv.x;
        u64t h0p[14];
#pragma unroll
        for (int kp = 0; kp < 14; ++kp) {
            float2 w  = *(const float2*)&sm[AW0 + 2 * kp];
            float2 bb = *(const float2*)&sm[AB0 + 2 * kp];
            h0p[kp] = pack2(tanhe(fmaf(s, w.x, bb.x)), tanhe(fmaf(s, w.y, bb.y)));
        }

        // ---- h1 (25->50): k-parity packed accumulate, 2 outputs per gp ----
        u64t h1p[26];
#pragma unroll
        for (int gp = 0; gp < 25; ++gp) {
            const ulonglong2* w0r = (const ulonglong2*)&sm[AW1T + (2 * gp) * 28];
            const ulonglong2* w1r = (const ulonglong2*)&sm[AW1T + (2 * gp + 1) * 28];
            u64t a0 = 0ull, a1 = 0ull;
#pragma unroll
            for (int q = 0; q < 7; ++q) {
                ulonglong2 wa = w0r[q], wb = w1r[q];
                a0 = ffma2(h0p[2 * q], wa.x, a0); a0 = ffma2(h0p[2 * q + 1], wa.y, a0);
                a1 = ffma2(h0p[2 * q], wb.x, a1); a1 = ffma2(h0p[2 * q + 1], wb.y, a1);
            }
            float l0, u0, l1, u1; unpack2(a0, l0, u0); unpack2(a1, l1, u1);
            const int g0 = 2 * gp, g1 = g0 + 1;
            const int q0 = g0 % 25, q1 = g1 % 25;
            float v0 = tanhe(l0 + u0 + sm[AB1 + g0]) + pget(h0p, q0);
            float v1 = tanhe(l1 + u1 + sm[AB1 + g1]) + pget(h0p, q1);
            h1p[gp] = pack2(v0, v1);
            *(float2*)&sm[AH1 + t * 50 + g0] = make_float2(v0, v1);
        }
        h1p[25] = 0ull;

        // ---- h2 (50->100): residual h1[g%50] is parity-aligned float2 ----
#pragma unroll 2
        for (int gp = 0; gp < 50; ++gp) {
            const int g0 = 2 * gp;
            const ulonglong2* w0r = (const ulonglong2*)&sm[AW2T + g0 * 52];
            const ulonglong2* w1r = (const ulonglong2*)&sm[AW2T + (g0 + 1) * 52];
            u64t a0 = 0ull, a1 = 0ull;
#pragma unroll
            for (int q = 0; q < 13; ++q) {
                ulonglong2 wa = w0r[q], wb = w1r[q];
                a0 = ffma2(h1p[2 * q], wa.x, a0); a0 = ffma2(h1p[2 * q + 1], wa.y, a0);
                a1 = ffma2(h1p[2 * q], wb.x, a1); a1 = ffma2(h1p[2 * q + 1], wb.y, a1);
            }
            float l0, u0, l1, u1; unpack2(a0, l0, u0); unpack2(a1, l1, u1);
            const int q0 = (g0 < 50) ? g0 : g0 - 50;
            float2 rv2 = *(const float2*)&sm[AH1 + t * 50 + q0];
            sm[AGT + g0 * 132 + t]       = tanhe(l0 + u0 + sm[AB2 + g0])     + rv2.x;
            sm[AGT + (g0 + 1) * 132 + t] = tanhe(l1 + u1 + sm[AB2 + g0 + 1]) + rv2.y;
        }
        __syncthreads();

        // ---- einsum: thread t<100 owns g=t; m-pair packed ----
        if (t < 100) {
            const ulonglong2* gr  = (const ulonglong2*)&sm[AGT + t * 132];
            const ulonglong2* c0r = (const ulonglong2*)&sm[ABLKT + 0 * 128];
            const ulonglong2* c1r = (const ulonglong2*)&sm[ABLKT + 1 * 128];
            const ulonglong2* c2r = (const ulonglong2*)&sm[ABLKT + 2 * 128];
            const ulonglong2* c3r = (const ulonglong2*)&sm[ABLKT + 3 * 128];
#pragma unroll 4
            for (int q = 0; q < 32; ++q) {
                ulonglong2 gv = gr[q];
                ulonglong2 b0 = c0r[q], b1 = c1r[q], b2 = c2r[q], b3 = c3r[q];
                axyz[0] = ffma2(gv.x, b0.x, axyz[0]); axyz[0] = ffma2(gv.y, b0.y, axyz[0]);
                axyz[1] = ffma2(gv.x, b1.x, axyz[1]); axyz[1] = ffma2(gv.y, b1.y, axyz[1]);
                axyz[2] = ffma2(gv.x, b2.x, axyz[2]); axyz[2] = ffma2(gv.y, b2.y, axyz[2]);
                axyz[3] = ffma2(gv.x, b3.x, axyz[3]); axyz[3] = ffma2(gv.y, b3.y, axyz[3]);
            }
        }
    }

    if (t < 100) {
        const float invn = 1.f / 256.f;
        float l, h;
        unpack2(axyz[0], l, h); sm[AXYZ + 0 * 100 + t] = (l + h) * invn;
        unpack2(axyz[1], l, h); sm[AXYZ + 1 * 100 + t] = (l + h) * invn;
        unpack2(axyz[2], l, h); sm[AXYZ + 2 * 100 + t] = (l + h) * invn;
        unpack2(axyz[3], l, h); sm[AXYZ + 3 * 100 + t] = (l + h) * invn;
    }
    __syncthreads();

    const int row = (i * BB + b) * NPER + n;
    float* drow = g_DR + (size_t)row * FIT_IN;
#pragma unroll 1
    for (int o = 0; o < 13; ++o) {
        int idx = t + o * 128;
        if (idx < FIT_IN) {
            int g = idx >> 4, h2i = idx & 15;
            float a = sm[AXYZ + 0 * 100 + g] * sm[AXYZ + 0 * 100 + h2i];
            a = fmaf(sm[AXYZ + 1 * 100 + g], sm[AXYZ + 1 * 100 + h2i], a);
            a = fmaf(sm[AXYZ + 2 * 100 + g], sm[AXYZ + 2 * 100 + h2i], a);
            a = fmaf(sm[AXYZ + 3 * 100 + g], sm[AXYZ + 3 * 100 + h2i], a);
            drow[idx] = a;
        }
    }
}

// ================= Kernel B: register-tiled chained fit GEMM =================
#define KT 32
#define SM_DR   0
#define SM_WS   25600
#define SM_ACTA (25600 + 2 * KT * FH)
#define SM_ACTB (SM_ACTA + 16 * FH)
#define B_SMEM_FLOATS (SM_ACTB + 16 * FH)

#define ROWF(r, D, WV) \
    acc[r][0] = fmaf(D, WV.x, acc[r][0]); acc[r][1] = fmaf(D, WV.y, acc[r][1]); \
    acc[r][2] = fmaf(D, WV.z, acc[r][2]); acc[r][3] = fmaf(D, WV.w, acc[r][3]);
#define STEP(WV, D0, D1, D2, D3) ROWF(0, D0, WV) ROWF(1, D1, WV) ROWF(2, D2, WV) ROWF(3, D3, WV)

__device__ __forceinline__ void run_layer(
    const float* __restrict__ Wg, const float* __restrict__ bg, int K,
    const float* __restrict__ dpan, int dstride,
    float* w_s, const float* __restrict__ res, float* __restrict__ outp,
    int tid, int ry, int c0)
{
    float acc[4][4];
    {
        float4 bv = *(const float4*)&bg[c0];
#pragma unroll
        for (int r = 0; r < 4; ++r) {
            acc[r][0] = bv.x; acc[r][1] = bv.y; acc[r][2] = bv.z; acc[r][3] = bv.w;
        }
    }
    const int T = (K + KT - 1) / KT;
    {
        int len0 = K < KT ? K : KT;
        for (int x = tid; x < len0 * 60; x += 256) {
            int kk = x / 60, seg = x - kk * 60;
            cp16(smaddr(w_s + kk * FH + seg * 4), Wg + (size_t)kk * FH + seg * 4);
        }
        cp_commit();
    }
#pragma unroll 1
    for (int t = 0; t < T; ++t) {
        const int kbase = t * KT;
        int len = K - kbase; if (len > KT) len = KT;
        if (t + 1 < T) {
            float* wnext = w_s + ((t + 1) & 1) * (KT * FH);
            const int kb2 = kbase + KT;
            int len2 = K - kb2; if (len2 > KT) len2 = KT;
            for (int x = tid; x < len2 * 60; x += 256) {
                int kk = x / 60, seg = x - kk * 60;
                cp16(smaddr(wnext + kk * FH + seg * 4), Wg + (size_t)(kb2 + kk) * FH + seg * 4);
            }
            cp_commit();
            asm volatile("cp.async.wait_group 1;" ::: "memory");
        } else {
            asm volatile("cp.async.wait_group 0;" ::: "memory");
        }
        __syncthreads();

        const float* wt = w_s + (t & 1) * (KT * FH);
        const float* dp = dpan + (size_t)(4 * ry) * dstride + kbase;
#pragma unroll 2
        for (int k4 = 0; k4 < len; k4 += 4) {
            float4 dv0 = *(const float4*)(dp + 0 * dstride + k4);
            float4 dv1 = *(const float4*)(dp + 1 * dstride + k4);
            float4 dv2 = *(const float4*)(dp + 2 * dstride + k4);
            float4 dv3 = *(const float4*)(dp + 3 * dstride + k4);
            float4 wv0 = *(const float4*)(wt + (k4 + 0) * FH + c0);
            float4 wv1 = *(const float4*)(wt + (k4 + 1) * FH + c0);
            float4 wv2 = *(const float4*)(wt + (k4 + 2) * FH + c0);
            float4 wv3 = *(const float4*)(wt + (k4 + 3) * FH + c0);
            STEP(wv0, dv0.x, dv1.x, dv2.x, dv3.x)
            STEP(wv1, dv0.y, dv1.y, dv2.y, dv3.y)
            STEP(wv2, dv0.z, dv1.z, dv2.z, dv3.z)
            STEP(wv3, dv0.w, dv1.w, dv2.w, dv3.w)
        }
        __syncthreads();
    }
#pragma unroll
    for (int r = 0; r < 4; ++r) {
        int row = 4 * ry + r;
        float4 o;
        o.x = tanhe(acc[r][0]); o.y = tanhe(acc[r][1]);
        o.z = tanhe(acc[r][2]); o.w = tanhe(acc[r][3]);
        if (res) {
            float4 rv = *(const float4*)&res[row * FH + c0];
            o.x += rv.x; o.y += rv.y; o.z += rv.z; o.w += rv.w;
        }
        *(float4*)&outp[row * FH + c0] = o;
    }
}

__global__ void __launch_bounds__(256, 1) fit_kernel(
    const float* __restrict__ W0, const float* __restrict__ b0,
    const float* __restrict__ W1, const float* __restrict__ b1,
    const float* __restrict__ W2, const float* __restrict__ b2,
    const float* __restrict__ W3, const float* __restrict__ b3,
    float* __restrict__ out)
{
    extern __shared__ float sm[];
    float* dr   = sm + SM_DR;
    float* w_s  = sm + SM_WS;
    float* actA = sm + SM_ACTA;
    float* actB = sm + SM_ACTB;

    const int tid = threadIdx.x;
    const int i = blockIdx.x >> 6;
    const int r0 = (blockIdx.x & 63) * 16;
    const int ry = tid >> 6;
    const int cx = tid & 63;
    const int cc = (cx < 60) ? cx : 59;
    const int c0 = cc * 4;

    const float* W0g = W0 + (size_t)i * FIT_IN * FH;
    const float* W1g = W1 + (size_t)i * FH * FH;
    const float* W2g = W2 + (size_t)i * FH * FH;
    const float* W3g = W3 + (size_t)i * FH;
    const float* b0g = b0 + i * FH;
    const float* b1g = b1 + i * FH;
    const float* b2g = b2 + i * FH;
    const float  b3v = b3[i];

    {
        const float* drg = g_DR + (size_t)(i * (BB * NPER) + r0) * FIT_IN;
        for (int x = tid; x < (16 * FIT_IN) / 4; x += 256)
            cp16(smaddr(dr + x * 4), drg + x * 4);
        cp_commit();
    }

    run_layer(W0g, b0g, FIT_IN, dr, FIT_IN, w_s, nullptr, actA, tid, ry, c0);
    __syncthreads();
    run_layer(W1g, b1g, FH, actA, FH, w_s, actA, actB, tid, ry, c0);
    __syncthreads();
    run_layer(W2g, b2g, FH, actB, FH, w_s, actB, actA, tid, ry, c0);
    __syncthreads();

    const int wi = tid >> 5, lane = tid & 31;
#pragma unroll 1
    for (int rr = 0; rr < 2; ++rr) {
        int r = wi * 2 + rr;
        float p = 0.f;
        for (int o2 = lane; o2 < FH; o2 += 32) p = fmaf(actA[r * FH + o2], W3g[o2], p);
#pragma unroll
        for (int sd = 16; sd > 0; sd >>= 1) p += __shfl_down_sync(0xffffffffu, p, sd);
        if (lane == 0) {
            int rowg = r0 + r;
            int bb = rowg >> 8, nn = rowg & 255;
            out[(bb * NT + i) * NPER + nn] = p + b3v;
        }
    }
}

// ---------------- launch ----------------
extern "C" void kernel_launch(void* const* d_in, const int* in_sizes, int n_in,
                              void* d_out, int out_size) {
    const float* Ri  = (const float*)d_in[0];
    const float* eW0 = (const float*)d_in[1];
    const float* eB0 = (const float*)d_in[2];
    const float* eW1 = (const float*)d_in[3];
    const float* eB1 = (const float*)d_in[4];
    const float* eW2 = (const float*)d_in[5];
    const float* eB2 = (const float*)d_in[6];
    const float* fW0 = (const float*)d_in[7];
    const float* fB0 = (const float*)d_in[8];
    const float* fW1 = (const float*)d_in[9];
    const float* fB1 = (const float*)d_in[10];
    const float* fW2 = (const float*)d_in[11];
    const float* fB2 = (const float*)d_in[12];
    const float* fW3 = (const float*)d_in[13];
    const float* fB3 = (const float*)d_in[14];
    float* out = (float*)d_out;

    cudaFuncSetAttribute(emb_dr_kernel, cudaFuncAttributeMaxDynamicSharedMemorySize,
                         A_SMEM * 4);
    cudaFuncSetAttribute(fit_kernel, cudaFuncAttributeMaxDynamicSharedMemorySize,
                         B_SMEM_FLOATS * 4);

    emb_dr_kernel<<<NROWS, 128, A_SMEM * 4>>>(Ri, eW0, eB0, eW1, eB1, eW2, eB2);
    fit_kernel<<<128, 256, B_SMEM_FLOATS * 4>>>(fW0, fB0, fW1, fB1, fW2, fB2, fW3, fB3, out);
}

// round 6
// speedup vs baseline: 1.5982x; 1.5982x over previous
#include <cuda_runtime.h>

#define NT 2
#define NPER 256
#define FIT_IN 1600
#define FH 240
#define BB 4
#define NROWS 2048
#define NKNOT 4097
#define SMIN (-8.f)
#define INVH 256.f

__device__ __align__(16) float g_DR[(size_t)NROWS * FIT_IN];
__device__ __align__(16) float g_tab[(size_t)4 * NKNOT * 100];

__device__ __forceinline__ float tanhe(float x) {
    float xa = fminf(fmaxf(x, -15.f), 15.f);
    float t = __expf(2.f * xa);
    return __fdividef(t - 1.f, t + 1.f);
}
__device__ __forceinline__ unsigned smaddr(const void* p) {
    unsigned a;
    asm("{.reg .u64 t; cvta.to.shared.u64 t, %1; cvt.u32.u64 %0, t;}" : "=r"(a) : "l"(p));
    return a;
}
__device__ __forceinline__ void cp16(unsigned dst, const void* src) {
    asm volatile("cp.async.ca.shared.global [%0], [%1], 16;" :: "r"(dst), "l"(src));
}
__device__ __forceinline__ void cp_commit() {
    asm volatile("cp.async.commit_group;" ::: "memory");
}

// ============ Kernel 0: tabulate embedding nets G(s) at 4097 knots ============
// dynamic smem offsets (floats)
#define TW0 0
#define TB0 25
#define TW1 50      // [25][50]
#define TB1 1300
#define TW2 1352    // [50][104]
#define TB2 6552
#define TH0 6652    // [128][26]
#define TH1 9980    // [128][52]
#define T_SMEM 16636

__global__ void __launch_bounds__(128) build_table_kernel(
    const float* __restrict__ eW0, const float* __restrict__ eB0,
    const float* __restrict__ eW1, const float* __restrict__ eB1,
    const float* __restrict__ eW2, const float* __restrict__ eB2)
{
    extern __shared__ float sm[];
    const int t = threadIdx.x;
    const int e = blockIdx.y;
    if (t < 25) { sm[TW0 + t] = eW0[e * 25 + t]; sm[TB0 + t] = eB0[e * 25 + t]; }
    for (int x = t; x < 1250; x += 128) sm[TW1 + x] = eW1[e * 1250 + x];
    if (t < 50) sm[TB1 + t] = eB1[e * 50 + t];
    for (int x = t; x < 5000; x += 128) { int k = x / 100, g = x - 100 * k; sm[TW2 + k * 104 + g] = eW2[e * 5000 + x]; }
    if (t < 100) sm[TB2 + t] = eB2[e * 100 + t];
    __syncthreads();

    const int idx = blockIdx.x * 128 + t;
    if (idx >= NKNOT) return;
    const float s = SMIN + (float)idx * (1.f / INVH);

    // h0
#pragma unroll 4
    for (int k = 0; k < 25; ++k)
        sm[TH0 + t * 26 + k] = tanhe(fmaf(s, sm[TW0 + k], sm[TB0 + k]));
    // h1
#pragma unroll 2
    for (int g = 0; g < 50; ++g) {
        float a = sm[TB1 + g];
#pragma unroll
        for (int k = 0; k < 25; ++k) a = fmaf(sm[TH0 + t * 26 + k], sm[TW1 + k * 50 + g], a);
        int q = g; if (q >= 25) q -= 25;
        sm[TH1 + t * 52 + g] = tanhe(a) + sm[TH0 + t * 26 + q];
    }
    // h2 -> table row
    float* row = g_tab + ((size_t)e * NKNOT + idx) * 100;
#pragma unroll 1
    for (int g4 = 0; g4 < 100; g4 += 4) {
        float a0 = sm[TB2 + g4 + 0], a1 = sm[TB2 + g4 + 1];
        float a2 = sm[TB2 + g4 + 2], a3 = sm[TB2 + g4 + 3];
#pragma unroll
        for (int k = 0; k < 50; ++k) {
            float4 w = *(const float4*)&sm[TW2 + k * 104 + g4];
            float hk = sm[TH1 + t * 52 + k];
            a0 = fmaf(hk, w.x, a0); a1 = fmaf(hk, w.y, a1);
            a2 = fmaf(hk, w.z, a2); a3 = fmaf(hk, w.w, a3);
        }
        int q0 = g4; if (q0 >= 50) q0 -= 50;
        float4 o;
        o.x = tanhe(a0) + sm[TH1 + t * 52 + q0];
        o.y = tanhe(a1) + sm[TH1 + t * 52 + q0 + 1];
        o.z = tanhe(a2) + sm[TH1 + t * 52 + q0 + 2];
        o.w = tanhe(a3) + sm[TH1 + t * 52 + q0 + 3];
        *(float4*)&row[g4] = o;
    }
}

// ============ Kernel A: table-lookup embedding + einsum + DR ============
// smem (floats): blk [128][4], G [128][104], xyz [4][100]
#define ABLK 0
#define AG   512
#define AXYZ 13824
#define A_SMEM 14224   // 56.9 KB -> 3 blocks/SM

__global__ void __launch_bounds__(128, 3) emb_dr_kernel(const float* __restrict__ Ri)
{
    extern __shared__ float sm[];
    const int t = threadIdx.x;
    const int blk = blockIdx.x;
    const int n = blk & 255;
    const int b = (blk >> 8) & 3;
    const int i = blk >> 10;

    const float* ri_base = Ri + ((size_t)((b * NT + i) * NPER + n)) * (NT * 128) * 4;
    const int tl = t & 3, mb = t >> 2;

    float acc0 = 0.f, acc1 = 0.f, acc2 = 0.f, acc3 = 0.f;

#pragma unroll 1
    for (int j = 0; j < NT; ++j) {
        __syncthreads();  // prior einsum reads done before restage
        float4 rv = *(const float4*)(ri_base + (size_t)(j * 128 + t) * 4);
        *(float4*)&sm[ABLK + 4 * t] = rv;
        __syncthreads();

        const float* tabe = g_tab + (size_t)(i * NT + j) * NKNOT * 100;
        // G fill: 4 threads per neighbor, 4 chunks of 32 neighbors
#pragma unroll 1
        for (int ch = 0; ch < 4; ++ch) {
            const int m = ch * 32 + mb;
            float s = sm[ABLK + 4 * m];
            float u = fminf(fmaxf((s - SMIN) * INVH, 0.f), 4095.0f);
            int k = (int)u;
            float f = u - (float)k;
            const float4* rl = (const float4*)(tabe + (size_t)k * 100);
#pragma unroll
            for (int q = 0; q < 7; ++q) {
                const int f4 = tl + 4 * q;
                if (f4 < 25) {
                    float4 lo = rl[f4];
                    float4 hi = rl[f4 + 25];   // next knot row (contiguous)
                    float4 o;
                    o.x = fmaf(f, hi.x - lo.x, lo.x);
                    o.y = fmaf(f, hi.y - lo.y, lo.y);
                    o.z = fmaf(f, hi.z - lo.z, lo.z);
                    o.w = fmaf(f, hi.w - lo.w, lo.w);
                    *(float4*)&sm[AG + m * 104 + 4 * f4] = o;
                }
            }
        }
        __syncthreads();

        // einsum: thread t<100 owns g=t
        if (t < 100) {
#pragma unroll 4
            for (int m = 0; m < 128; ++m) {
                float gv = sm[AG + m * 104 + t];
                float4 bv = *(const float4*)&sm[ABLK + 4 * m];
                acc0 = fmaf(bv.x, gv, acc0);
                acc1 = fmaf(bv.y, gv, acc1);
                acc2 = fmaf(bv.z, gv, acc2);
                acc3 = fmaf(bv.w, gv, acc3);
            }
        }
    }

    if (t < 100) {
        const float invn = 1.f / 256.f;
        sm[AXYZ + 0 * 100 + t] = acc0 * invn;
        sm[AXYZ + 1 * 100 + t] = acc1 * invn;
        sm[AXYZ + 2 * 100 + t] = acc2 * invn;
        sm[AXYZ + 3 * 100 + t] = acc3 * invn;
    }
    __syncthreads();

    const int row = (i * BB + b) * NPER + n;
    float* drow = g_DR + (size_t)row * FIT_IN;
#pragma unroll 1
    for (int o = 0; o < 13; ++o) {
        int idx = t + o * 128;
        if (idx < FIT_IN) {
            int g = idx >> 4, h = idx & 15;
            float a = sm[AXYZ + 0 * 100 + g] * sm[AXYZ + 0 * 100 + h];
            a = fmaf(sm[AXYZ + 1 * 100 + g], sm[AXYZ + 1 * 100 + h], a);
            a = fmaf(sm[AXYZ + 2 * 100 + g], sm[AXYZ + 2 * 100 + h], a);
            a = fmaf(sm[AXYZ + 3 * 100 + g], sm[AXYZ + 3 * 100 + h], a);
            drow[idx] = a;
        }
    }
}

// ============ Kernel B: fit net, 8-row tiles, 2 blocks/SM ============
#define KT 16
#define SM_DR   0                    // 8*1600 = 12800
#define SM_WS   12800                // 2*16*240 = 7680
#define SM_ACTA 20480                // 8*240 = 1920
#define SM_ACTB 22400                // 1920
#define B_SMEM  24320                // floats = 97.3 KB

#define ROWF2(r, D, WV) \
    acc[r][0] = fmaf(D, WV.x, acc[r][0]); acc[r][1] = fmaf(D, WV.y, acc[r][1]); \
    acc[r][2] = fmaf(D, WV.z, acc[r][2]); acc[r][3] = fmaf(D, WV.w, acc[r][3]);
#define STEP2(WV, D0, D1) ROWF2(0, D0, WV) ROWF2(1, D1, WV)

__device__ __forceinline__ void run_layer8(
    const float* __restrict__ Wg, const float* __restrict__ bg, int K,
    const float* __restrict__ dpan, int dstride,
    float* w_s, const float* __restrict__ res, float* __restrict__ outp,
    int tid, int ry, int c0)
{
    float acc[2][4];
    {
        float4 bv = *(const float4*)&bg[c0];
        acc[0][0] = bv.x; acc[0][1] = bv.y; acc[0][2] = bv.z; acc[0][3] = bv.w;
        acc[1][0] = bv.x; acc[1][1] = bv.y; acc[1][2] = bv.z; acc[1][3] = bv.w;
    }
    const int T = K / KT;   // K is a multiple of 16 (1600, 240)

    // prologue: stage tile 0
    for (int x = tid; x < KT * 60; x += 256) {
        int kk = x / 60, seg = x - kk * 60;
        cp16(smaddr(w_s + kk * FH + seg * 4), Wg + (size_t)kk * FH + seg * 4);
    }
    cp_commit();

#pragma unroll 1
    for (int t = 0; t < T; ++t) {
        if (t + 1 < T) {
            float* wnext = w_s + ((t + 1) & 1) * (KT * FH);
            const float* wgn = Wg + (size_t)(t + 1) * KT * FH;
            for (int x = tid; x < KT * 60; x += 256) {
                int kk = x / 60, seg = x - kk * 60;
                cp16(smaddr(wnext + kk * FH + seg * 4), wgn + (size_t)kk * FH + seg * 4);
            }
            cp_commit();
            asm volatile("cp.async.wait_group 1;" ::: "memory");
        } else {
            asm volatile("cp.async.wait_group 0;" ::: "memory");
        }
        __syncthreads();

        const float* wt = w_s + (t & 1) * (KT * FH);
        const float* dp = dpan + (size_t)(2 * ry) * dstride + t * KT;
#pragma unroll
        for (int k4 = 0; k4 < KT; k4 += 4) {
            float4 d0 = *(const float4*)(dp + k4);
            float4 d1 = *(const float4*)(dp + dstride + k4);
            float4 wv0 = *(const float4*)(wt + (k4 + 0) * FH + c0);
            float4 wv1 = *(const float4*)(wt + (k4 + 1) * FH + c0);
            float4 wv2 = *(const float4*)(wt + (k4 + 2) * FH + c0);
            float4 wv3 = *(const float4*)(wt + (k4 + 3) * FH + c0);
            STEP2(wv0, d0.x, d1.x)
            STEP2(wv1, d0.y, d1.y)
            STEP2(wv2, d0.z, d1.z)
            STEP2(wv3, d0.w, d1.w)
        }
        __syncthreads();
    }

    // epilogue: tanh (+res); threads with cx>=60 duplicate col group 59 (benign)
#pragma unroll
    for (int r = 0; r < 2; ++r) {
        int row = 2 * ry + r;
        float4 o;
        o.x = tanhe(acc[r][0]); o.y = tanhe(acc[r][1]);
        o.z = tanhe(acc[r][2]); o.w = tanhe(acc[r][3]);
        if (res) {
            float4 rv = *(const float4*)&res[row * FH + c0];
            o.x += rv.x; o.y += rv.y; o.z += rv.z; o.w += rv.w;
        }
        *(float4*)&outp[row * FH + c0] = o;
    }
}

__global__ void __launch_bounds__(256, 2) fit_kernel(
    const float* __restrict__ W0, const float* __restrict__ b0,
    const float* __restrict__ W1, const float* __restrict__ b1,
    const float* __restrict__ W2, const float* __restrict__ b2,
    const float* __restrict__ W3, const float* __restrict__ b3,
    float* __restrict__ out)
{
    extern __shared__ float sm[];
    float* dr   = sm + SM_DR;
    float* w_s  = sm + SM_WS;
    float* actA = sm + SM_ACTA;
    float* actB = sm + SM_ACTB;

    const int tid = threadIdx.x;
    const int i = blockIdx.x >> 7;
    const int r0 = (blockIdx.x & 127) * 8;
    const int ry = tid >> 6;
    const int cx = tid & 63;
    const int cc = (cx < 60) ? cx : 59;
    const int c0 = cc * 4;

    const float* W0g = W0 + (size_t)i * FIT_IN * FH;
    const float* W1g = W1 + (size_t)i * FH * FH;
    const float* W2g = W2 + (size_t)i * FH * FH;
    const float* W3g = W3 + (size_t)i * FH;
    const float* b0g = b0 + i * FH;
    const float* b1g = b1 + i * FH;
    const float* b2g = b2 + i * FH;
    const float  b3v = b3[i];

    {
        const float* drg = g_DR + (size_t)(i * (BB * NPER) + r0) * FIT_IN;
        for (int x = tid; x < (8 * FIT_IN) / 4; x += 256)
            cp16(smaddr(dr + 4 * x), drg + 4 * x);
        cp_commit();
    }

    run_layer8(W0g, b0g, FIT_IN, dr, FIT_IN, w_s, nullptr, actA, tid, ry, c0);
    __syncthreads();
    run_layer8(W1g, b1g, FH, actA, FH, w_s, actA, actB, tid, ry, c0);
    __syncthreads();
    run_layer8(W2g, b2g, FH, actB, FH, w_s, actB, actA, tid, ry, c0);
    __syncthreads();

    // final 240 -> 1: warp wi handles row wi
    const int wi = tid >> 5, lane = tid & 31;
    float p = 0.f;
    for (int o2 = lane; o2 < FH; o2 += 32) p = fmaf(actA[wi * FH + o2], W3g[o2], p);
#pragma unroll
    for (int sd = 16; sd > 0; sd >>= 1) p += __shfl_down_sync(0xffffffffu, p, sd);
    if (lane == 0) {
        int rowg = r0 + wi;
        int bb = rowg >> 8, nn = rowg & 255;
        out[(bb * NT + i) * NPER + nn] = p + b3v;
    }
}

// ---------------- launch ----------------
extern "C" void kernel_launch(void* const* d_in, const int* in_sizes, int n_in,
                              void* d_out, int out_size) {
    const float* Ri  = (const float*)d_in[0];
    const float* eW0 = (const float*)d_in[1];
    const float* eB0 = (const float*)d_in[2];
    const float* eW1 = (const float*)d_in[3];
    const float* eB1 = (const float*)d_in[4];
    const float* eW2 = (const float*)d_in[5];
    const float* eB2 = (const float*)d_in[6];
    const float* fW0 = (const float*)d_in[7];
    const float* fB0 = (const float*)d_in[8];
    const float* fW1 = (const float*)d_in[9];
    const float* fB1 = (const float*)d_in[10];
    const float* fW2 = (const float*)d_in[11];
    const float* fB2 = (const float*)d_in[12];
    const float* fW3 = (const float*)d_in[13];
    const float* fB3 = (const float*)d_in[14];
    float* out = (float*)d_out;

    cudaFuncSetAttribute(build_table_kernel, cudaFuncAttributeMaxDynamicSharedMemorySize,
                         T_SMEM * 4);
    cudaFuncSetAttribute(emb_dr_kernel, cudaFuncAttributeMaxDynamicSharedMemorySize,
                         A_SMEM * 4);
    cudaFuncSetAttribute(fit_kernel, cudaFuncAttributeMaxDynamicSharedMemorySize,
                         B_SMEM * 4);

    build_table_kernel<<<dim3(33, 4), 128, T_SMEM * 4>>>(eW0, eB0, eW1, eB1, eW2, eB2);
    emb_dr_kernel<<<NROWS, 128, A_SMEM * 4>>>(Ri);
    fit_kernel<<<256, 256, B_SMEM * 4>>>(fW0, fB0, fW1, fB1, fW2, fB2, fW3, fB3, out);
}

// round 7
// speedup vs baseline: 1.6251x; 1.0169x over previous
#include <cuda_runtime.h>

#define NT 2
#define NPER 256
#define FIT_IN 1600
#define FH 240
#define BB 4
#define NROWS 2048
#define NKNOT 8193          // knots; interp rows 0..8191
#define NROWT 8192
#define SMIN (-8.f)
#define INVH 512.f

__device__ __align__(16) float g_DR[(size_t)NROWS * FIT_IN];
// interleaved table: [e][k][g] -> float2 {G_k[g], G_{k+1}[g]}
__device__ __align__(16) float g_tab[(size_t)4 * NROWT * 100 * 2];

__device__ __forceinline__ float tanhe(float x) {
    float xa = fminf(fmaxf(x, -15.f), 15.f);
    float t = __expf(2.f * xa);
    return __fdividef(t - 1.f, t + 1.f);
}
__device__ __forceinline__ unsigned smaddr(const void* p) {
    unsigned a;
    asm("{.reg .u64 t; cvta.to.shared.u64 t, %1; cvt.u32.u64 %0, t;}" : "=r"(a) : "l"(p));
    return a;
}
__device__ __forceinline__ void cp16(unsigned dst, const void* src) {
    asm volatile("cp.async.ca.shared.global [%0], [%1], 16;" :: "r"(dst), "l"(src));
}
__device__ __forceinline__ void cp_commit() {
    asm volatile("cp.async.commit_group;" ::: "memory");
}

// ============ Kernel 0: tabulate G(s), register-resident MLP ============
// smem: weights only
#define TW0 0
#define TB0 28
#define TW1 56      // [25][50]
#define TB1 1308
#define TW2 1360    // [50][104]
#define TB2 6560
#define T_SMEM 6660

__global__ void __launch_bounds__(256) build_table_kernel(
    const float* __restrict__ eW0, const float* __restrict__ eB0,
    const float* __restrict__ eW1, const float* __restrict__ eB1,
    const float* __restrict__ eW2, const float* __restrict__ eB2)
{
    extern __shared__ float sm[];
    const int t = threadIdx.x;
    const int e = blockIdx.y;
    if (t < 25) { sm[TW0 + t] = eW0[e * 25 + t]; sm[TB0 + t] = eB0[e * 25 + t]; }
    for (int x = t; x < 1250; x += 256) sm[TW1 + x] = eW1[e * 1250 + x];
    if (t < 50) sm[TB1 + t] = eB1[e * 50 + t];
    for (int x = t; x < 5000; x += 256) { int k = x / 100, g = x - 100 * k; sm[TW2 + k * 104 + g] = eW2[e * 5000 + x]; }
    if (t < 100) sm[TB2 + t] = eB2[e * 100 + t];
    __syncthreads();

    const int idx = blockIdx.x * 256 + t;
    if (idx >= NKNOT) return;
    const float s = SMIN + (float)idx * (1.f / INVH);

    float h0[25];
#pragma unroll
    for (int k = 0; k < 25; ++k)
        h0[k] = tanhe(fmaf(s, sm[TW0 + k], sm[TB0 + k]));

    float h1[50];
#pragma unroll
    for (int gp = 0; gp < 25; ++gp) {
        float a0 = sm[TB1 + 2 * gp], a1 = sm[TB1 + 2 * gp + 1];
#pragma unroll
        for (int k = 0; k < 25; ++k) {
            float2 w = *(const float2*)&sm[TW1 + k * 50 + 2 * gp];
            a0 = fmaf(h0[k], w.x, a0);
            a1 = fmaf(h0[k], w.y, a1);
        }
        h1[2 * gp]     = tanhe(a0) + h0[(2 * gp) % 25];
        h1[2 * gp + 1] = tanhe(a1) + h0[(2 * gp + 1) % 25];
    }

    float* tabe = g_tab + (size_t)e * NROWT * 200;
#pragma unroll 1
    for (int g4 = 0; g4 < 100; g4 += 4) {
        float a0 = sm[TB2 + g4 + 0], a1 = sm[TB2 + g4 + 1];
        float a2 = sm[TB2 + g4 + 2], a3 = sm[TB2 + g4 + 3];
#pragma unroll
        for (int k = 0; k < 50; ++k) {
            float4 w = *(const float4*)&sm[TW2 + k * 104 + g4];
            float hk = h1[k];
            a0 = fmaf(hk, w.x, a0); a1 = fmaf(hk, w.y, a1);
            a2 = fmaf(hk, w.z, a2); a3 = fmaf(hk, w.w, a3);
        }
        const int q0 = g4 % 50;
        float o[4];
        o[0] = tanhe(a0) + h1[q0];
        o[1] = tanhe(a1) + h1[q0 + 1];
        o[2] = tanhe(a2) + h1[q0 + 2];
        o[3] = tanhe(a3) + h1[q0 + 3];
        // write lo half of row idx, hi half of row idx-1
#pragma unroll
        for (int q = 0; q < 4; ++q) {
            const int g = g4 + q;
            if (idx < NROWT) tabe[(size_t)idx * 200 + 2 * g] = o[q];
            if (idx > 0)     tabe[(size_t)(idx - 1) * 200 + 2 * g + 1] = o[q];
        }
    }
}

// ============ Kernel A: fused table-interp einsum + DR ============
// smem: blk [128][4], k[128](int), f[128], xyz [4][100]
#define SBLK 0
#define SKI  512
#define SFR  640
#define SXYZ 768
#define A_SMEM 1168

__global__ void __launch_bounds__(128) emb_dr_kernel(const float* __restrict__ Ri)
{
    extern __shared__ float sm[];
    int* smi = (int*)sm;
    const int t = threadIdx.x;
    const int blk = blockIdx.x;
    const int n = blk & 255;
    const int b = (blk >> 8) & 3;
    const int i = blk >> 10;

    const float* ri_base = Ri + ((size_t)((b * NT + i) * NPER + n)) * (NT * 128) * 4;

    float acc0 = 0.f, acc1 = 0.f, acc2 = 0.f, acc3 = 0.f;

#pragma unroll 1
    for (int j = 0; j < NT; ++j) {
        __syncthreads();  // prior einsum reads done before restage
        float4 rv = *(const float4*)(ri_base + (size_t)(j * 128 + t) * 4);
        *(float4*)&sm[SBLK + 4 * t] = rv;
        float u = fminf(fmaxf((rv.x - SMIN) * INVH, 0.f), 8191.0f);
        int kk = (int)u;
        smi[SKI + t] = kk;
        sm[SFR + t] = u - (float)kk;
        __syncthreads();

        if (t < 100) {
            const float* tabe = g_tab + (size_t)(i * NT + j) * NROWT * 200;
#pragma unroll 4
            for (int m = 0; m < 128; ++m) {
                const int km = smi[SKI + m];
                const float fm = sm[SFR + m];
                float2 v = *(const float2*)(tabe + (size_t)km * 200 + 2 * t);
                float gv = fmaf(fm, v.y - v.x, v.x);
                float4 bv = *(const float4*)&sm[SBLK + 4 * m];
                acc0 = fmaf(bv.x, gv, acc0);
                acc1 = fmaf(bv.y, gv, acc1);
                acc2 = fmaf(bv.z, gv, acc2);
                acc3 = fmaf(bv.w, gv, acc3);
            }
        }
    }

    if (t < 100) {
        const float invn = 1.f / 256.f;
        sm[SXYZ + 0 * 100 + t] = acc0 * invn;
        sm[SXYZ + 1 * 100 + t] = acc1 * invn;
        sm[SXYZ + 2 * 100 + t] = acc2 * invn;
        sm[SXYZ + 3 * 100 + t] = acc3 * invn;
    }
    __syncthreads();

    const int row = (i * BB + b) * NPER + n;
    float* drow = g_DR + (size_t)row * FIT_IN;
#pragma unroll 1
    for (int o = 0; o < 13; ++o) {
        int idx = t + o * 128;
        if (idx < FIT_IN) {
            int g = idx >> 4, h = idx & 15;
            float a = sm[SXYZ + 0 * 100 + g] * sm[SXYZ + 0 * 100 + h];
            a = fmaf(sm[SXYZ + 1 * 100 + g], sm[SXYZ + 1 * 100 + h], a);
            a = fmaf(sm[SXYZ + 2 * 100 + g], sm[SXYZ + 2 * 100 + h], a);
            a = fmaf(sm[SXYZ + 3 * 100 + g], sm[SXYZ + 3 * 100 + h], a);
            drow[idx] = a;
        }
    }
}

// ============ Kernel B: fit net, 8-row tiles, 2 blocks/SM ============
#define KT 16
#define SM_DR   0
#define SM_WS   12800
#define SM_ACTA 20480
#define SM_ACTB 22400
#define B_SMEM  24320

#define ROWF2(r, D, WV) \
    acc[r][0] = fmaf(D, WV.x, acc[r][0]); acc[r][1] = fmaf(D, WV.y, acc[r][1]); \
    acc[r][2] = fmaf(D, WV.z, acc[r][2]); acc[r][3] = fmaf(D, WV.w, acc[r][3]);
#define STEP2(WV, D0, D1) ROWF2(0, D0, WV) ROWF2(1, D1, WV)

__device__ __forceinline__ void run_layer8(
    const float* __restrict__ Wg, const float* __restrict__ bg, int K,
    const float* __restrict__ dpan, int dstride,
    float* w_s, const float* __restrict__ res, float* __restrict__ outp,
    int tid, int ry, int c0)
{
    float acc[2][4];
    {
        float4 bv = *(const float4*)&bg[c0];
        acc[0][0] = bv.x; acc[0][1] = bv.y; acc[0][2] = bv.z; acc[0][3] = bv.w;
        acc[1][0] = bv.x; acc[1][1] = bv.y; acc[1][2] = bv.z; acc[1][3] = bv.w;
    }
    const int T = K / KT;

    for (int x = tid; x < KT * 60; x += 256) {
        int kk = x / 60, seg = x - kk * 60;
        cp16(smaddr(w_s + kk * FH + seg * 4), Wg + (size_t)kk * FH + seg * 4);
    }
    cp_commit();

#pragma unroll 1
    for (int t = 0; t < T; ++t) {
        if (t + 1 < T) {
            float* wnext = w_s + ((t + 1) & 1) * (KT * FH);
            const float* wgn = Wg + (size_t)(t + 1) * KT * FH;
            for (int x = tid; x < KT * 60; x += 256) {
                int kk = x / 60, seg = x - kk * 60;
                cp16(smaddr(wnext + kk * FH + seg * 4), wgn + (size_t)kk * FH + seg * 4);
            }
            cp_commit();
            asm volatile("cp.async.wait_group 1;" ::: "memory");
        } else {
            asm volatile("cp.async.wait_group 0;" ::: "memory");
        }
        __syncthreads();

        const float* wt = w_s + (t & 1) * (KT * FH);
        const float* dp = dpan + (size_t)(2 * ry) * dstride + t * KT;
#pragma unroll
        for (int k4 = 0; k4 < KT; k4 += 4) {
            float4 d0 = *(const float4*)(dp + k4);
            float4 d1 = *(const float4*)(dp + dstride + k4);
            float4 wv0 = *(const float4*)(wt + (k4 + 0) * FH + c0);
            float4 wv1 = *(const float4*)(wt + (k4 + 1) * FH + c0);
            float4 wv2 = *(const float4*)(wt + (k4 + 2) * FH + c0);
            float4 wv3 = *(const float4*)(wt + (k4 + 3) * FH + c0);
            STEP2(wv0, d0.x, d1.x)
            STEP2(wv1, d0.y, d1.y)
            STEP2(wv2, d0.z, d1.z)
            STEP2(wv3, d0.w, d1.w)
        }
        __syncthreads();
    }

#pragma unroll
    for (int r = 0; r < 2; ++r) {
        int row = 2 * ry + r;
        float4 o;
        o.x = tanhe(acc[r][0]); o.y = tanhe(acc[r][1]);
        o.z = tanhe(acc[r][2]); o.w = tanhe(acc[r][3]);
        if (res) {
            float4 rv = *(const float4*)&res[row * FH + c0];
            o.x += rv.x; o.y += rv.y; o.z += rv.z; o.w += rv.w;
        }
        *(float4*)&outp[row * FH + c0] = o;
    }
}

__global__ void __launch_bounds__(256, 2) fit_kernel(
    const float* __restrict__ W0, const float* __restrict__ b0,
    const float* __restrict__ W1, const float* __restrict__ b1,
    const float* __restrict__ W2, const float* __restrict__ b2,
    const float* __restrict__ W3, const float* __restrict__ b3,
    float* __restrict__ out)
{
    extern __shared__ float sm[];
    float* dr   = sm + SM_DR;
    float* w_s  = sm + SM_WS;
    float* actA = sm + SM_ACTA;
    float* actB = sm + SM_ACTB;

    const int tid = threadIdx.x;
    const int i = blockIdx.x >> 7;
    const int r0 = (blockIdx.x & 127) * 8;
    const int ry = tid >> 6;
    const int cx = tid & 63;
    const int cc = (cx < 60) ? cx : 59;
    const int c0 = cc * 4;

    const float* W0g = W0 + (size_t)i * FIT_IN * FH;
    const float* W1g = W1 + (size_t)i * FH * FH;
    const float* W2g = W2 + (size_t)i * FH * FH;
    const float* W3g = W3 + (size_t)i * FH;
    const float* b0g = b0 + i * FH;
    const float* b1g = b1 + i * FH;
    const float* b2g = b2 + i * FH;
    const float  b3v = b3[i];

    {
        const float* drg = g_DR + (size_t)(i * (BB * NPER) + r0) * FIT_IN;
        for (int x = tid; x < (8 * FIT_IN) / 4; x += 256)
            cp16(smaddr(dr + 4 * x), drg + 4 * x);
        cp_commit();
    }

    run_layer8(W0g, b0g, FIT_IN, dr, FIT_IN, w_s, nullptr, actA, tid, ry, c0);
    __syncthreads();
    run_layer8(W1g, b1g, FH, actA, FH, w_s, actA, actB, tid, ry, c0);
    __syncthreads();
    run_layer8(W2g, b2g, FH, actB, FH, w_s, actB, actA, tid, ry, c0);
    __syncthreads();

    const int wi = tid >> 5, lane = tid & 31;
    float p = 0.f;
    for (int o2 = lane; o2 < FH; o2 += 32) p = fmaf(actA[wi * FH + o2], W3g[o2], p);
#pragma unroll
    for (int sd = 16; sd > 0; sd >>= 1) p += __shfl_down_sync(0xffffffffu, p, sd);
    if (lane == 0) {
        int rowg = r0 + wi;
        int bb = rowg >> 8, nn = rowg & 255;
        out[(bb * NT + i) * NPER + nn] = p + b3v;
    }
}

// ---------------- launch ----------------
extern "C" void kernel_launch(void* const* d_in, const int* in_sizes, int n_in,
                              void* d_out, int out_size) {
    const float* Ri  = (const float*)d_in[0];
    const float* eW0 = (const float*)d_in[1];
    const float* eB0 = (const float*)d_in[2];
    const float* eW1 = (const float*)d_in[3];
    const float* eB1 = (const float*)d_in[4];
    const float* eW2 = (const float*)d_in[5];
    const float* eB2 = (const float*)d_in[6];
    const float* fW0 = (const float*)d_in[7];
    const float* fB0 = (const float*)d_in[8];
    const float* fW1 = (const float*)d_in[9];
    const float* fB1 = (const float*)d_in[10];
    const float* fW2 = (const float*)d_in[11];
    const float* fB2 = (const float*)d_in[12];
    const float* fW3 = (const float*)d_in[13];
    const float* fB3 = (const float*)d_in[14];
    float* out = (float*)d_out;

    cudaFuncSetAttribute(build_table_kernel, cudaFuncAttributeMaxDynamicSharedMemorySize,
                         T_SMEM * 4);
    cudaFuncSetAttribute(emb_dr_kernel, cudaFuncAttributeMaxDynamicSharedMemorySize,
                         A_SMEM * 4);
    cudaFuncSetAttribute(fit_kernel, cudaFuncAttributeMaxDynamicSharedMemorySize,
                         B_SMEM * 4);

    build_table_kernel<<<dim3(33, 4), 256, T_SMEM * 4>>>(eW0, eB0, eW1, eB1, eW2, eB2);
    emb_dr_kernel<<<NROWS, 128, A_SMEM * 4>>>(Ri);
    fit_kernel<<<256, 256, B_SMEM * 4>>>(fW0, fB0, fW1, fB1, fW2, fB2, fW3, fB3, out);
}